// round 2
// baseline (speedup 1.0000x reference)
#include <cuda_runtime.h>
#include <math.h>

#define MUL0 16
#define MUL1 8
#define DIM_F 40
#define NRB 16
#define NRD 64
#define W_NUMEL 576

#define THREADS 576
#define WARPS 18
#define E_TILE 16
#define GRID 148

struct __align__(16) Smem {
    float W2s[NRD * W_NUMEL];     // 36864
    float W1s[NRB * NRD];         // 1024  [i][d]
    float h[NRD][E_TILE];         // 1024  post-silu, includes /8
    float emb[E_TILE][NRB];       // 256
    float x[E_TILE][DIM_F];       // 640
    float dotv[E_TILE][MUL1];     // 128   includes 1/sqrt(3)
    float sh1[E_TILE][3];         // 48    sqrt(3)*unit
    float rr[E_TILE];
    float pA[12][16][E_TILE];     // out0 partials: 8 (w00) + 4 (w11)
    float pB[4][8][E_TILE];       // w01 cf partials
    float pC[2][8][3][E_TILE];    // w10 partials
    int   src[E_TILE];
    int   dst[E_TILE];
};

__device__ __forceinline__ float silu_f(float z) {
    return z / (1.0f + expf(-z));
}

__global__ void zero_kernel(float4* __restrict__ out, int n4) {
    int i = blockIdx.x * blockDim.x + threadIdx.x;
    if (i < n4) out[i] = make_float4(0.f, 0.f, 0.f, 0.f);
}

__global__ __launch_bounds__(THREADS, 1)
void conv_kernel(const float* __restrict__ pos,
                 const float* __restrict__ f_in,
                 const int*   __restrict__ edge_src,
                 const int*   __restrict__ edge_dst,
                 const float* __restrict__ W1,
                 const float* __restrict__ W2,
                 float* __restrict__ f_out,
                 int n_edges)
{
    extern __shared__ char smem_raw[];
    Smem* s = reinterpret_cast<Smem*>(smem_raw);

    const int tid  = threadIdx.x;
    const int warp = tid >> 5;
    const int lane = tid & 31;
    const int col  = warp * 32 + lane;

    // ---- Stage weights once ----
    {
        const float4* src4 = reinterpret_cast<const float4*>(W2);
        float4* dst4 = reinterpret_cast<float4*>(s->W2s);
        for (int i = tid; i < (NRD * W_NUMEL) / 4; i += THREADS) dst4[i] = src4[i];
        for (int i = tid; i < NRB * NRD; i += THREADS) s->W1s[i] = W1[i];
    }
    __syncthreads();

    const int n_tiles = (n_edges + E_TILE - 1) / E_TILE;

    for (int tile = blockIdx.x; tile < n_tiles; tile += gridDim.x) {
        // ---- Phase 1: geometry (threads 0..15) ----
        if (tid < E_TILE) {
            int e = tile * E_TILE + tid;
            if (e < n_edges) {
                int es = edge_src[e], ed = edge_dst[e];
                float ax = pos[es * 3 + 0], ay = pos[es * 3 + 1], az = pos[es * 3 + 2];
                float bx = pos[ed * 3 + 0], by = pos[ed * 3 + 1], bz = pos[ed * 3 + 2];
                float dx = bx - ax, dy = by - ay, dz = bz - az;
                float r = sqrtf(dx * dx + dy * dy + dz * dz + 1e-12f);
                float inv = 1.7320508075688772f / r;     // sqrt(3)/r
                s->src[tid] = es;
                s->dst[tid] = ed;
                s->rr[tid]  = r;
                s->sh1[tid][0] = dx * inv;
                s->sh1[tid][1] = dy * inv;
                s->sh1[tid][2] = dz * inv;
            } else {
                s->src[tid] = 0; s->dst[tid] = 0;
                s->rr[tid] = 1e9f;
                s->sh1[tid][0] = 0.f; s->sh1[tid][1] = 0.f; s->sh1[tid][2] = 0.f;
            }
        }
        __syncthreads();

        // ---- Phase 2: radial embedding (threads 0..255) + x gather ----
        if (tid < E_TILE * NRB) {
            int e = tid >> 4, i = tid & 15;
            float v = (5.0f / 17.0f) * (float)(i + 1);
            float d = (s->rr[e] - v) * (17.0f / 5.0f);
            float y = 0.0f;
            if (fabsf(d) < 1.0f)
                y = 4.56544f * expf(2.0f - 1.0f / (1.0f + d) - 1.0f / (1.0f - d));
            s->emb[e][i] = y;
        }
        for (int idx = tid; idx < E_TILE * DIM_F; idx += THREADS) {
            int e = idx / DIM_F, c = idx - e * DIM_F;
            s->x[e][c] = f_in[s->src[e] * DIM_F + c];
        }
        __syncthreads();

        // ---- Phase 3: h = silu(emb@W1/4)/8  and dot ----
        for (int idx = tid; idx < NRD * E_TILE; idx += THREADS) {
            int d = idx >> 4, e = idx & 15;
            float z = 0.0f;
            #pragma unroll
            for (int i = 0; i < NRB; i++)
                z += s->emb[e][i] * s->W1s[i * NRD + d];
            s->h[d][e] = silu_f(z * 0.25f) * 0.125f;
        }
        if (tid < E_TILE * MUL1) {
            int e = tid >> 3, u = tid & 7;
            float dv = s->x[e][16 + u * 3 + 0] * s->sh1[e][0]
                     + s->x[e][16 + u * 3 + 1] * s->sh1[e][1]
                     + s->x[e][16 + u * 3 + 2] * s->sh1[e][2];
            s->dotv[e][u] = dv * 0.57735026918962576f;   // 1/sqrt(3)
        }
        __syncthreads();

        // ---- Phase 4: GEMV (f32x2, 16 edges) ----
        unsigned long long acc[8];
        #pragma unroll
        for (int p = 0; p < 8; p++) acc[p] = 0ULL;
        {
            const float* wcol = s->W2s + col;
            #pragma unroll 4
            for (int d = 0; d < NRD; d++) {
                float wv = wcol[d * W_NUMEL];
                unsigned long long wp;
                asm("mov.b64 %0, {%1, %1};" : "=l"(wp) : "f"(wv));
                const ulonglong2* hp = reinterpret_cast<const ulonglong2*>(s->h[d]);
                #pragma unroll
                for (int q = 0; q < 4; q++) {
                    ulonglong2 hv = hp[q];
                    asm("fma.rn.f32x2 %0, %1, %2, %0;" : "+l"(acc[2*q  ]) : "l"(hv.x), "l"(wp));
                    asm("fma.rn.f32x2 %0, %1, %2, %0;" : "+l"(acc[2*q+1]) : "l"(hv.y), "l"(wp));
                }
            }
        }
        // unpack w values
        float wv[E_TILE];
        #pragma unroll
        for (int p = 0; p < 8; p++)
            asm("mov.b64 {%0, %1}, %2;" : "=f"(wv[2*p]), "=f"(wv[2*p+1]) : "l"(acc[p]));

        // ---- Tensor product via shuffle reductions (no atomics) ----
        if (warp < 8) {                       // w00: u = 2w + (lane>>4), v = lane&15
            int u = 2 * warp + (lane >> 4);
            int v = lane & 15;
            #pragma unroll
            for (int e = 0; e < E_TILE; e++) {
                float t = wv[e] * s->x[e][u];
                t += __shfl_xor_sync(0xffffffffu, t, 16);
                if (lane < 16) s->pA[warp][v][e] = t;
            }
        } else if (warp < 12) {               // w01: u = 4(w-8)+(lane>>3), wp = lane&7
            int u = 4 * (warp - 8) + (lane >> 3);
            int wp_ = lane & 7;
            #pragma unroll
            for (int e = 0; e < E_TILE; e++) {
                float t = wv[e] * s->x[e][u];
                t += __shfl_xor_sync(0xffffffffu, t, 8);
                t += __shfl_xor_sync(0xffffffffu, t, 16);
                if (lane < 8) s->pB[warp - 8][wp_][e] = t;
            }
        } else if (warp < 14) {               // w10: u = 4(w-12)+(lane>>3), wp = lane&7
            int u = 4 * (warp - 12) + (lane >> 3);
            int wp_ = lane & 7;
            #pragma unroll
            for (int e = 0; e < E_TILE; e++) {
                float t0 = wv[e] * s->x[e][16 + u * 3 + 0];
                float t1 = wv[e] * s->x[e][16 + u * 3 + 1];
                float t2 = wv[e] * s->x[e][16 + u * 3 + 2];
                t0 += __shfl_xor_sync(0xffffffffu, t0, 8);
                t0 += __shfl_xor_sync(0xffffffffu, t0, 16);
                t1 += __shfl_xor_sync(0xffffffffu, t1, 8);
                t1 += __shfl_xor_sync(0xffffffffu, t1, 16);
                t2 += __shfl_xor_sync(0xffffffffu, t2, 8);
                t2 += __shfl_xor_sync(0xffffffffu, t2, 16);
                if (lane < 8) {
                    s->pC[warp - 12][wp_][0][e] = t0;
                    s->pC[warp - 12][wp_][1][e] = t1;
                    s->pC[warp - 12][wp_][2][e] = t2;
                }
            }
        } else {                              // w11: u = 2(w-14)+(lane>>4), v = lane&15
            int u = 2 * (warp - 14) + (lane >> 4);
            int v = lane & 15;
            #pragma unroll
            for (int e = 0; e < E_TILE; e++) {
                float t = wv[e] * s->dotv[e][u];
                t += __shfl_xor_sync(0xffffffffu, t, 16);
                if (lane < 16) s->pA[8 + (warp - 14)][v][e] = t;
            }
        }
        __syncthreads();

        // ---- Phase 5: final reduce + global scatter ----
        {
            const float SCALE = 0.05103103630798288f;   // 1/(sqrt(24)*sqrt(16))
            for (int idx = tid; idx < E_TILE * DIM_F; idx += THREADS) {
                int e = idx / DIM_F, c = idx - e * DIM_F;
                float v;
                if (c < MUL0) {
                    v = 0.0f;
                    #pragma unroll
                    for (int sslot = 0; sslot < 12; sslot++)
                        v += s->pA[sslot][c][e];
                } else {
                    int q = c - MUL0;
                    int wp_ = q / 3, kk = q - wp_ * 3;
                    float cf = s->pB[0][wp_][e] + s->pB[1][wp_][e]
                             + s->pB[2][wp_][e] + s->pB[3][wp_][e];
                    v = cf * s->sh1[e][kk]
                      + s->pC[0][wp_][kk][e] + s->pC[1][wp_][kk][e];
                }
                atomicAdd(&f_out[s->dst[e] * DIM_F + c], v * SCALE);
            }
        }
        __syncthreads();
    }
}

extern "C" void kernel_launch(void* const* d_in, const int* in_sizes, int n_in,
                              void* d_out, int out_size) {
    const float* pos  = (const float*)d_in[0];
    const float* f_in = (const float*)d_in[1];
    const int*   esrc = (const int*)d_in[2];
    const int*   edst = (const int*)d_in[3];
    const float* W1   = (const float*)d_in[4];
    const float* W2   = (const float*)d_in[5];
    float* out = (float*)d_out;
    int n_edges = in_sizes[2];

    static int smem_set = 0;
    cudaFuncSetAttribute(conv_kernel, cudaFuncAttributeMaxDynamicSharedMemorySize,
                         (int)sizeof(Smem));
    (void)smem_set;

    int n4 = out_size / 4;
    zero_kernel<<<(n4 + 255) / 256, 256>>>((float4*)out, n4);
    conv_kernel<<<GRID, THREADS, sizeof(Smem)>>>(pos, f_in, esrc, edst, W1, W2, out, n_edges);
}

// round 3
// speedup vs baseline: 2.4538x; 2.4538x over previous
#include <cuda_runtime.h>
#include <math.h>

#define MUL0 16
#define MUL1 8
#define DIM_F 40
#define NRB 16
#define NRD 64
#define W_NUMEL 576

#define THREADS 448
#define WARPS 14
#define E_TILE 8
#define GRID 148

struct __align__(16) WarpScratch {
    float h[NRD][E_TILE];     // 2048 B  post-silu, includes /8
    float x[E_TILE][DIM_F];   // 1280 B
    float emb[E_TILE][NRB];   // 512 B
    float dotv[E_TILE][MUL1]; // 256 B  includes 1/sqrt(3)
    float sh1[E_TILE][4];     // 128 B  sqrt(3)*unit
    float rr[E_TILE];         // 32 B
    int   src[E_TILE];        // 32 B
    int   dst[E_TILE];        // 32 B
    float pad[8];             // 32 B -> 4352 B total
};

#define W2_FLOATS (NRD * W_NUMEL)   // 36864
#define W1_FLOATS (NRB * NRD)       // 1024
#define SMEM_BYTES ((W2_FLOATS + W1_FLOATS) * 4 + WARPS * (int)sizeof(WarpScratch))

__device__ __forceinline__ float silu_scaled(float z) {
    // returns silu(z*0.25)/8, via tanh.approx: silu(a) = a*0.5*(1+tanh(a/2))
    float a = z * 0.25f;
    float th;
    asm("tanh.approx.f32 %0, %1;" : "=f"(th) : "f"(a * 0.5f));
    return a * (1.0f + th) * 0.0625f;   // 0.5 * 0.125
}

__global__ void zero_kernel(float4* __restrict__ out, int n4) {
    int i = blockIdx.x * blockDim.x + threadIdx.x;
    if (i < n4) out[i] = make_float4(0.f, 0.f, 0.f, 0.f);
}

__global__ __launch_bounds__(THREADS, 1)
void conv_kernel(const float* __restrict__ pos,
                 const float* __restrict__ f_in,
                 const int*   __restrict__ edge_src,
                 const int*   __restrict__ edge_dst,
                 const float* __restrict__ W1,
                 const float* __restrict__ W2,
                 float* __restrict__ f_out,
                 int n_edges)
{
    extern __shared__ float smem[];
    float* W2s = smem;
    float* W1s = smem + W2_FLOATS;
    WarpScratch* wsArr = reinterpret_cast<WarpScratch*>(smem + W2_FLOATS + W1_FLOATS);

    const int tid  = threadIdx.x;
    const int warp = tid >> 5;
    const int lane = tid & 31;
    WarpScratch* ws = &wsArr[warp];

    // ---- Stage weights once per block ----
    {
        const float4* src4 = reinterpret_cast<const float4*>(W2);
        float4* dst4 = reinterpret_cast<float4*>(W2s);
        for (int i = tid; i < W2_FLOATS / 4; i += THREADS) dst4[i] = src4[i];
        for (int i = tid; i < W1_FLOATS; i += THREADS) W1s[i] = W1[i];
    }
    __syncthreads();

    const int n_groups = (n_edges + E_TILE - 1) / E_TILE;
    const int gw = blockIdx.x * WARPS + warp;
    const int nw = gridDim.x * WARPS;

    for (int g = gw; g < n_groups; g += nw) {
        __syncwarp();
        // ---- Phase A: geometry (lanes 0..7) ----
        if (lane < E_TILE) {
            int e = g * E_TILE + lane;
            if (e < n_edges) {
                int es = edge_src[e], ed = edge_dst[e];
                float ax = pos[es * 3 + 0], ay = pos[es * 3 + 1], az = pos[es * 3 + 2];
                float bx = pos[ed * 3 + 0], by = pos[ed * 3 + 1], bz = pos[ed * 3 + 2];
                float dx = bx - ax, dy = by - ay, dz = bz - az;
                float r = sqrtf(dx * dx + dy * dy + dz * dz + 1e-12f);
                float inv = 1.7320508075688772f / r;   // sqrt(3)/r
                ws->src[lane] = es;
                ws->dst[lane] = ed;
                ws->rr[lane]  = r;
                ws->sh1[lane][0] = dx * inv;
                ws->sh1[lane][1] = dy * inv;
                ws->sh1[lane][2] = dz * inv;
            } else {
                ws->src[lane] = 0; ws->dst[lane] = 0;
                ws->rr[lane] = 1e9f;
                ws->sh1[lane][0] = 0.f; ws->sh1[lane][1] = 0.f; ws->sh1[lane][2] = 0.f;
            }
        }
        __syncwarp();
        // ---- Phase B: radial embedding + x gather ----
        #pragma unroll
        for (int t = 0; t < 4; t++) {               // 128 items: e x i
            int idx = lane + 32 * t;
            int e = idx >> 4, i = idx & 15;
            float v = (5.0f / 17.0f) * (float)(i + 1);
            float d = (ws->rr[e] - v) * 3.4f;       // 17/5
            float y = 0.0f;
            float d2 = d * d;
            if (d2 < 1.0f) {
                // 4.56544 * exp(2 - 2/(1-d^2))
                y = 4.56544f * __expf(2.0f - __fdividef(2.0f, 1.0f - d2));
            }
            ws->emb[e][i] = y;
        }
        #pragma unroll
        for (int t = 0; t < 10; t++) {              // 320 items: x gather
            int idx = lane + 32 * t;
            int e = idx / DIM_F, c = idx - e * DIM_F;
            ws->x[e][c] = f_in[ws->src[e] * DIM_F + c];
        }
        __syncwarp();
        // ---- Phase C: h = silu(emb@W1/4)/8 ; dotv ----
        #pragma unroll
        for (int p = 0; p < 2; p++) {
            int d = lane + 32 * p;
            float w1c[NRB];
            #pragma unroll
            for (int i = 0; i < NRB; i++) w1c[i] = W1s[i * NRD + d];
            float hz[E_TILE];
            #pragma unroll
            for (int e = 0; e < E_TILE; e++) {
                float z = 0.0f;
                #pragma unroll
                for (int i = 0; i < NRB; i++) z += ws->emb[e][i] * w1c[i];
                hz[e] = silu_scaled(z);
            }
            float4 hA = make_float4(hz[0], hz[1], hz[2], hz[3]);
            float4 hB = make_float4(hz[4], hz[5], hz[6], hz[7]);
            *reinterpret_cast<float4*>(&ws->h[d][0]) = hA;
            *reinterpret_cast<float4*>(&ws->h[d][4]) = hB;
        }
        #pragma unroll
        for (int t = 0; t < 2; t++) {               // dotv: 64 items
            int idx = lane + 32 * t;
            int e = idx >> 3, u = idx & 7;
            float dv = ws->x[e][16 + u * 3 + 0] * ws->sh1[e][0]
                     + ws->x[e][16 + u * 3 + 1] * ws->sh1[e][1]
                     + ws->x[e][16 + u * 3 + 2] * ws->sh1[e][2];
            ws->dotv[e][u] = dv * 0.57735026918962576f;  // 1/sqrt(3)
        }
        __syncwarp();

        // ---- Phase D: GEMV (3 passes of 6 columns) + register TP ----
        float po0[E_TILE], cf[E_TILE], t0a[E_TILE], t1a[E_TILE], t2a[E_TILE];
        #pragma unroll
        for (int e = 0; e < E_TILE; e++) {
            po0[e] = 0.f; cf[e] = 0.f; t0a[e] = 0.f; t1a[e] = 0.f; t2a[e] = 0.f;
        }

        #pragma unroll
        for (int pass = 0; pass < 3; pass++) {
            const int jb = pass * 6;
            unsigned long long acc[6][4];
            #pragma unroll
            for (int j6 = 0; j6 < 6; j6++)
                #pragma unroll
                for (int p = 0; p < 4; p++) acc[j6][p] = 0ULL;

            const float* wbase = W2s + jb * 32 + lane;
            #pragma unroll 2
            for (int d = 0; d < NRD; d++) {
                const ulonglong2* hp = reinterpret_cast<const ulonglong2*>(ws->h[d]);
                ulonglong2 h01 = hp[0];
                ulonglong2 h45 = hp[1];
                const float* row = wbase + d * W_NUMEL;
                #pragma unroll
                for (int j6 = 0; j6 < 6; j6++) {
                    float wv = row[j6 * 32];
                    unsigned long long wp;
                    asm("mov.b64 %0, {%1, %1};" : "=l"(wp) : "f"(wv));
                    asm("fma.rn.f32x2 %0, %1, %2, %0;" : "+l"(acc[j6][0]) : "l"(h01.x), "l"(wp));
                    asm("fma.rn.f32x2 %0, %1, %2, %0;" : "+l"(acc[j6][1]) : "l"(h01.y), "l"(wp));
                    asm("fma.rn.f32x2 %0, %1, %2, %0;" : "+l"(acc[j6][2]) : "l"(h45.x), "l"(wp));
                    asm("fma.rn.f32x2 %0, %1, %2, %0;" : "+l"(acc[j6][3]) : "l"(h45.y), "l"(wp));
                }
            }
            // TP for the 6 columns of this pass (j compile-time)
            #pragma unroll
            for (int j6 = 0; j6 < 6; j6++) {
                const int j = jb + j6;
                float wvv[E_TILE];
                #pragma unroll
                for (int p = 0; p < 4; p++)
                    asm("mov.b64 {%0, %1}, %2;"
                        : "=f"(wvv[2*p]), "=f"(wvv[2*p+1]) : "l"(acc[j6][p]));
                if (j < 8) {                          // w00: u=2j+(lane>>4), v=lane&15
                    int u = 2 * j + (lane >> 4);
                    #pragma unroll
                    for (int e = 0; e < E_TILE; e++)
                        po0[e] = fmaf(wvv[e], ws->x[e][u], po0[e]);
                } else if (j < 12) {                  // w01: u=4(j-8)+(lane>>3)
                    int u = 4 * (j - 8) + (lane >> 3);
                    #pragma unroll
                    for (int e = 0; e < E_TILE; e++)
                        cf[e] = fmaf(wvv[e], ws->x[e][u], cf[e]);
                } else if (j < 14) {                  // w10: u=4(j-12)+(lane>>3)
                    int u = 4 * (j - 12) + (lane >> 3);
                    #pragma unroll
                    for (int e = 0; e < E_TILE; e++) {
                        t0a[e] = fmaf(wvv[e], ws->x[e][16 + u * 3 + 0], t0a[e]);
                        t1a[e] = fmaf(wvv[e], ws->x[e][16 + u * 3 + 1], t1a[e]);
                        t2a[e] = fmaf(wvv[e], ws->x[e][16 + u * 3 + 2], t2a[e]);
                    }
                } else {                              // w11: u=2(j-14)+(lane>>4)
                    int u = 2 * (j - 14) + (lane >> 4);
                    #pragma unroll
                    for (int e = 0; e < E_TILE; e++)
                        po0[e] = fmaf(wvv[e], ws->dotv[e][u], po0[e]);
                }
            }
        }

        // ---- Phase E: shuffle reductions + global scatter ----
        {
            const float SCALE = 0.05103103630798288f;   // 1/(sqrt(24)*sqrt(16))
            #pragma unroll
            for (int e = 0; e < E_TILE; e++) {
                float o0 = po0[e] + __shfl_xor_sync(0xffffffffu, po0[e], 16);
                float c_ = cf[e];
                c_ += __shfl_xor_sync(0xffffffffu, c_, 8);
                c_ += __shfl_xor_sync(0xffffffffu, c_, 16);
                float a0 = t0a[e];
                a0 += __shfl_xor_sync(0xffffffffu, a0, 8);
                a0 += __shfl_xor_sync(0xffffffffu, a0, 16);
                float a1 = t1a[e];
                a1 += __shfl_xor_sync(0xffffffffu, a1, 8);
                a1 += __shfl_xor_sync(0xffffffffu, a1, 16);
                float a2 = t2a[e];
                a2 += __shfl_xor_sync(0xffffffffu, a2, 8);
                a2 += __shfl_xor_sync(0xffffffffu, a2, 16);
                int d_ = ws->dst[e];
                if (lane < 16)
                    atomicAdd(&f_out[d_ * DIM_F + lane], o0 * SCALE);
                if (lane < 8) {
                    float s0 = ws->sh1[e][0], s1 = ws->sh1[e][1], s2 = ws->sh1[e][2];
                    float* base = &f_out[d_ * DIM_F + 16 + 3 * lane];
                    atomicAdd(base + 0, (c_ * s0 + a0) * SCALE);
                    atomicAdd(base + 1, (c_ * s1 + a1) * SCALE);
                    atomicAdd(base + 2, (c_ * s2 + a2) * SCALE);
                }
            }
        }
    }
}

extern "C" void kernel_launch(void* const* d_in, const int* in_sizes, int n_in,
                              void* d_out, int out_size) {
    const float* pos  = (const float*)d_in[0];
    const float* f_in = (const float*)d_in[1];
    const int*   esrc = (const int*)d_in[2];
    const int*   edst = (const int*)d_in[3];
    const float* W1   = (const float*)d_in[4];
    const float* W2   = (const float*)d_in[5];
    float* out = (float*)d_out;
    int n_edges = in_sizes[2];

    cudaFuncSetAttribute(conv_kernel, cudaFuncAttributeMaxDynamicSharedMemorySize, SMEM_BYTES);

    int n4 = out_size / 4;
    zero_kernel<<<(n4 + 255) / 256, 256>>>((float4*)out, n4);
    conv_kernel<<<GRID, THREADS, SMEM_BYTES>>>(pos, f_in, esrc, edst, W1, W2, out, n_edges);
}